// round 4
// baseline (speedup 1.0000x reference)
#include <cuda_runtime.h>
#include <cstdint>

#define N_NODES 50000
#define EMAX 1600000
#define LDA 144
#define GBLK 782         // ceil(N_NODES/64)
#define SB 512
#define NB 98            // ceil(N_NODES/512)

typedef unsigned long long u64;

// ---------------- scratch (static __device__, no allocation) ----------------
__device__ float g_A[N_NODES * LDA];      // layer-1 GEMM input, stride 144 (cols 134..143 stay 0)
__device__ float g_h1[N_NODES * 128];     // relu output layer 1
__device__ float g_uv[N_NODES * 128];     // cols 0..63 = h1@W2_nbr, cols 64..127 = h1@W2_root
__device__ float g_h2[N_NODES * 64];      // final embeddings
__device__ float g_deginv[N_NODES];
__device__ int   g_deg[N_NODES];
__device__ int   g_cur[N_NODES];
__device__ int   g_rowptr[N_NODES + 1];
__device__ int   g_bsum[NB];
__device__ int   g_boff[NB];
__device__ int   g_csr[EMAX];             // src ids bucketed by dst
__device__ int   g_eid[EMAX];             // original edge id bucketed by dst
__device__ float g_W1[144 * 128];
__device__ float g_W2[128 * 128];

// ---------------- f32x2 helpers ----------------
__device__ __forceinline__ u64 pk(float lo, float hi) {
    u64 r; asm("mov.b64 %0, {%1,%2};" : "=l"(r) : "f"(lo), "f"(hi)); return r;
}
__device__ __forceinline__ float2 upk(u64 v) {
    float2 r; asm("mov.b64 {%0,%1}, %2;" : "=f"(r.x), "=f"(r.y) : "l"(v)); return r;
}
__device__ __forceinline__ void ffma2(u64 &d, u64 a, u64 b) {
    asm("fma.rn.f32x2 %0, %1, %2, %0;" : "+l"(d) : "l"(a), "l"(b));
}

// ---------------- small kernels ----------------
__global__ void k_zero() {
    int t0 = blockIdx.x * blockDim.x + threadIdx.x;
    int stride = gridDim.x * blockDim.x;
    for (int i = t0; i < N_NODES; i += stride) { g_deg[i] = 0; g_cur[i] = 0; }
}

__global__ void k_prepw(const float* __restrict__ W1r, const float* __restrict__ W1n,
                        const float* __restrict__ W2r, const float* __restrict__ W2n) {
    int t0 = blockIdx.x * blockDim.x + threadIdx.x;
    int stride = gridDim.x * blockDim.x;
    for (int i = t0; i < 144 * 128; i += stride) {
        int r = i >> 7, c = i & 127;
        float v = 0.0f;
        if (r < 66) v = W1r[r * 128 + c];
        else if (r >= 68 && r < 134) v = W1n[(r - 68) * 128 + c];
        g_W1[i] = v;
    }
    for (int i = t0; i < 128 * 128; i += stride) {
        int r = i >> 7, c = i & 127;
        g_W2[i] = (c < 64) ? W2n[r * 64 + c] : W2r[r * 64 + (c - 64)];
    }
}

__global__ void k_deg(const int* __restrict__ dst, int E) {
    int i = blockIdx.x * blockDim.x + threadIdx.x;
    if (i < E) atomicAdd(&g_deg[dst[i]], 1);
}

__global__ void k_scan1() {
    __shared__ int s[SB];
    int tid = threadIdx.x;
    int i = blockIdx.x * SB + tid;
    int v = (i < N_NODES) ? g_deg[i] : 0;
    s[tid] = v;
    __syncthreads();
    #pragma unroll
    for (int off = 1; off < SB; off <<= 1) {
        int t = (tid >= off) ? s[tid - off] : 0;
        __syncthreads();
        s[tid] += t;
        __syncthreads();
    }
    if (i < N_NODES) g_rowptr[i] = s[tid] - v;
    if (tid == SB - 1) g_bsum[blockIdx.x] = s[tid];
}

__global__ void k_scan2() {
    if (threadIdx.x == 0 && blockIdx.x == 0) {
        int run = 0;
        for (int b = 0; b < NB; b++) { g_boff[b] = run; run += g_bsum[b]; }
    }
}

__global__ void k_scan3(int E) {
    int i = blockIdx.x * blockDim.x + threadIdx.x;
    if (i < N_NODES) {
        g_rowptr[i] += g_boff[i / SB];
        g_deginv[i] = 1.0f / fmaxf((float)g_deg[i], 1.0f);
    }
    if (i == 0) g_rowptr[N_NODES] = E;
}

__global__ void k_fillcsr(const int* __restrict__ src, const int* __restrict__ dst, int E) {
    int e = blockIdx.x * blockDim.x + threadIdx.x;
    if (e >= E) return;
    int d = dst[e];
    int ofs = atomicAdd(&g_cur[d], 1);
    int pos = g_rowptr[d] + ofs;
    g_csr[pos] = src[e];
    g_eid[pos] = e;
}

// A cols 0..67 = concat(x, pos, 0, 0)
__global__ void k_buildA1(const float* __restrict__ x, const float* __restrict__ pos) {
    int i = blockIdx.x * blockDim.x + threadIdx.x;
    if (i >= N_NODES * 68) return;
    int n = i / 68, c = i % 68;
    float v = 0.0f;
    if (c < 64) v = x[n * 64 + c];
    else if (c < 66) v = pos[n * 2 + (c - 64)];
    g_A[(size_t)n * LDA + c] = v;
}

// ---------------- gather-side aggregation, layer 1 ----------------
__global__ __launch_bounds__(256) void k_agg1(const float* __restrict__ x,
                                              const float* __restrict__ pos) {
    int gt = blockIdx.x * blockDim.x + threadIdx.x;
    int w = gt >> 5, lane = gt & 31;
    if (w >= N_NODES) return;
    int start = g_rowptr[w], end = g_rowptr[w + 1];
    float ax = 0.f, ay = 0.f, px = 0.f, py = 0.f;
    const float2* x2 = (const float2*)x;
    const float2* p2 = (const float2*)pos;
    for (int i = start; i < end; i += 32) {
        int m = min(32, end - i);
        int eid = (i + lane < end) ? g_csr[i + lane] : 0;
        for (int j = 0; j < m; j++) {
            int s = __shfl_sync(0xffffffffu, eid, j);
            float2 v = __ldg(x2 + (size_t)s * 32 + lane);
            ax += v.x; ay += v.y;
            if (lane == 0) { float2 p = __ldg(p2 + s); px += p.x; py += p.y; }
        }
    }
    float di = g_deginv[w];
    float* rowp = g_A + (size_t)w * LDA;
    rowp[68 + lane * 2]     = ax * di;
    rowp[68 + lane * 2 + 1] = ay * di;
    if (lane == 0) { rowp[132] = px * di; rowp[133] = py * di; }
}

// ---------------- GEMM with packed f32x2 FMA ----------------
// C[M,128] = A[M,K] @ B[K,128]. 64-row blocks, 256 threads,
// thread (ty,tx): rows ty*4..+4, cols tx*8..+8 (contiguous).
template <int MODE>
__global__ __launch_bounds__(256) void k_gemm(const float* __restrict__ bias) {
    const int K   = (MODE == 0) ? 144 : 128;
    const int lda = (MODE == 0) ? 144 : 128;
    const float* __restrict__ A = (MODE == 0) ? g_A : g_h1;
    const float* __restrict__ B = (MODE == 0) ? g_W1 : g_W2;
    float* __restrict__ C       = (MODE == 0) ? g_h1 : g_uv;

    __shared__ float As[16][68];   // transposed A tile; 68*4=272B rows keep 16B alignment
    __shared__ float Bs[16][128];

    int tid = threadIdx.x;
    int block_row = blockIdx.x * 64;
    int arow = tid >> 2, acol4 = tid & 3;           // A tile: 64 rows x 4 float4
    int brow = tid >> 5, bcol4 = tid & 31;          // B tile: 8(+8) rows x 32 float4
    int ty = tid >> 4, tx = tid & 15;
    int a_grow = min(block_row + arow, N_NODES - 1);

    u64 acc[4][4];
    #pragma unroll
    for (int i = 0; i < 4; i++)
        #pragma unroll
        for (int m = 0; m < 4; m++) acc[i][m] = 0ull;

    for (int k0 = 0; k0 < K; k0 += 16) {
        float4 av  = *(const float4*)(A + (size_t)a_grow * lda + k0 + acol4 * 4);
        float4 bv0 = *(const float4*)(B + (size_t)(k0 + brow) * 128 + bcol4 * 4);
        float4 bv1 = *(const float4*)(B + (size_t)(k0 + brow + 8) * 128 + bcol4 * 4);
        __syncthreads();
        As[acol4 * 4 + 0][arow] = av.x;
        As[acol4 * 4 + 1][arow] = av.y;
        As[acol4 * 4 + 2][arow] = av.z;
        As[acol4 * 4 + 3][arow] = av.w;
        *(float4*)&Bs[brow][bcol4 * 4] = bv0;
        *(float4*)&Bs[brow + 8][bcol4 * 4] = bv1;
        __syncthreads();
        #pragma unroll
        for (int kk = 0; kk < 16; kk++) {
            float4 a4 = *(const float4*)&As[kk][ty * 4];
            float4 b0 = *(const float4*)&Bs[kk][tx * 8];
            float4 b1 = *(const float4*)&Bs[kk][tx * 8 + 4];
            u64 bp[4];
            bp[0] = pk(b0.x, b0.y); bp[1] = pk(b0.z, b0.w);
            bp[2] = pk(b1.x, b1.y); bp[3] = pk(b1.z, b1.w);
            u64 ap[4];
            ap[0] = pk(a4.x, a4.x); ap[1] = pk(a4.y, a4.y);
            ap[2] = pk(a4.z, a4.z); ap[3] = pk(a4.w, a4.w);
            #pragma unroll
            for (int i = 0; i < 4; i++)
                #pragma unroll
                for (int m = 0; m < 4; m++)
                    ffma2(acc[i][m], ap[i], bp[m]);
        }
    }

    float4 bias0, bias1;
    if (MODE == 0) {
        bias0 = ((const float4*)bias)[tx * 2];
        bias1 = ((const float4*)bias)[tx * 2 + 1];
    }
    #pragma unroll
    for (int i = 0; i < 4; i++) {
        int r = block_row + ty * 4 + i;
        if (r >= N_NODES) break;
        float2 c0 = upk(acc[i][0]), c1 = upk(acc[i][1]);
        float2 c2 = upk(acc[i][2]), c3 = upk(acc[i][3]);
        float4 v0 = make_float4(c0.x, c0.y, c1.x, c1.y);
        float4 v1 = make_float4(c2.x, c2.y, c3.x, c3.y);
        if (MODE == 0) {
            v0.x = fmaxf(v0.x + bias0.x, 0.f); v0.y = fmaxf(v0.y + bias0.y, 0.f);
            v0.z = fmaxf(v0.z + bias0.z, 0.f); v0.w = fmaxf(v0.w + bias0.w, 0.f);
            v1.x = fmaxf(v1.x + bias1.x, 0.f); v1.y = fmaxf(v1.y + bias1.y, 0.f);
            v1.z = fmaxf(v1.z + bias1.z, 0.f); v1.w = fmaxf(v1.w + bias1.w, 0.f);
        }
        *(float4*)&C[(size_t)r * 128 + tx * 8]     = v0;
        *(float4*)&C[(size_t)r * 128 + tx * 8 + 4] = v1;
    }
}

// ---------------- gather-side aggregation, layer 2 (+ fused final) ----------------
__global__ __launch_bounds__(256) void k_agg2(const float* __restrict__ b2) {
    int gt = blockIdx.x * blockDim.x + threadIdx.x;
    int w = gt >> 5, lane = gt & 31;
    if (w >= N_NODES) return;
    int start = g_rowptr[w], end = g_rowptr[w + 1];
    float ax = 0.f, ay = 0.f;
    const float2* uv2 = (const float2*)g_uv;
    for (int i = start; i < end; i += 32) {
        int m = min(32, end - i);
        int eid = (i + lane < end) ? g_csr[i + lane] : 0;
        for (int j = 0; j < m; j++) {
            int s = __shfl_sync(0xffffffffu, eid, j);
            float2 v = __ldg(uv2 + (size_t)s * 64 + lane);
            ax += v.x; ay += v.y;
        }
    }
    float di = g_deginv[w];
    float rx = g_uv[(size_t)w * 128 + 64 + lane * 2];
    float ry = g_uv[(size_t)w * 128 + 64 + lane * 2 + 1];
    g_h2[(size_t)w * 64 + lane * 2]     = rx + ax * di + b2[lane * 2];
    g_h2[(size_t)w * 64 + lane * 2 + 1] = ry + ay * di + b2[lane * 2 + 1];
}

// ---------------- edge dot via CSR: warp per dst node ----------------
__global__ __launch_bounds__(256) void k_edge2(float* __restrict__ out) {
    int gt = blockIdx.x * blockDim.x + threadIdx.x;
    int w = gt >> 5, lane = gt & 31;
    if (w >= N_NODES) return;
    int start = g_rowptr[w], end = g_rowptr[w + 1];
    const float2* h2_2 = (const float2*)g_h2;
    float2 hd = h2_2[(size_t)w * 32 + lane];          // dst row stays in registers
    for (int i = start; i < end; i += 32) {
        int m = min(32, end - i);
        int s = 0, eid = 0;
        if (i + lane < end) { s = g_csr[i + lane]; eid = g_eid[i + lane]; }
        float res = 0.f;
        for (int j = 0; j < m; j++) {
            int sj = __shfl_sync(0xffffffffu, s, j);
            float2 v = __ldg(h2_2 + (size_t)sj * 32 + lane);
            float p = hd.x * v.x + hd.y * v.y;
            p += __shfl_xor_sync(0xffffffffu, p, 16);
            p += __shfl_xor_sync(0xffffffffu, p, 8);
            p += __shfl_xor_sync(0xffffffffu, p, 4);
            p += __shfl_xor_sync(0xffffffffu, p, 2);
            p += __shfl_xor_sync(0xffffffffu, p, 1);
            if (lane == j) res = p;
        }
        if (i + lane < end) out[eid] = res;
    }
}

// ---------------- launch ----------------
extern "C" void kernel_launch(void* const* d_in, const int* in_sizes, int n_in,
                              void* d_out, int out_size) {
    const float* x   = (const float*)d_in[0];
    const float* pos = (const float*)d_in[1];
    const int*   ei  = (const int*)d_in[2];
    const float* W1r = (const float*)d_in[3];
    const float* W1n = (const float*)d_in[4];
    const float* b1  = (const float*)d_in[5];
    const float* W2r = (const float*)d_in[6];
    const float* W2n = (const float*)d_in[7];
    const float* b2  = (const float*)d_in[8];
    float* out = (float*)d_out;

    int E = in_sizes[2] / 2;
    const int* src = ei;
    const int* dst = ei + E;

    k_zero<<<64, 256>>>();
    k_prepw<<<80, 256>>>(W1r, W1n, W2r, W2n);
    k_deg<<<(E + 255) / 256, 256>>>(dst, E);
    k_scan1<<<NB, SB>>>();
    k_scan2<<<1, 32>>>();
    k_scan3<<<(N_NODES + 255) / 256, 256>>>(E);
    k_fillcsr<<<(E + 255) / 256, 256>>>(src, dst, E);
    k_buildA1<<<(N_NODES * 68 + 255) / 256, 256>>>(x, pos);
    k_agg1<<<(N_NODES * 32 + 255) / 256, 256>>>(x, pos);
    k_gemm<0><<<GBLK, 256>>>(b1);
    k_gemm<1><<<GBLK, 256>>>(b1);
    k_agg2<<<(N_NODES * 32 + 255) / 256, 256>>>(b2);
    k_edge2<<<(N_NODES * 32 + 255) / 256, 256>>>(out);
}